// round 13
// baseline (speedup 1.0000x reference)
#include <cuda_runtime.h>
#include <cuda_fp16.h>
#include <mma.h>
#include <math.h>
#include <stdint.h>

using namespace nvcuda;

#define N_NODES   100000
#define DEG       16
#define IN_DIM    128
#define OUT_DIM   32
#define EPS       1e-8f

// One 128B line per node: uint2[0..7] = 32 halves (z fp16, dims 4j..4j+3 in
// slot j), uint2[8].x = inorm fp32 bits, rest pad (never read).
__device__ __align__(128) uint2 g_rows[N_NODES][16];

__device__ __forceinline__ float2 h2f(uint32_t u) {
    __half2 h = *reinterpret_cast<__half2*>(&u);
    return __half22float2(h);
}

// ---------------------------------------------------------------------------
// Kernel 1: z = h @ W^T via wmma FP16 (m16n16k16), fp32 accumulate.
// One CTA per 64-row tile (1563 CTAs), 256 threads = 8 warps, 26.1KB smem.
// Epilogue writes the packed 128B row (fp16 z + fp32 inorm).
// ---------------------------------------------------------------------------
#define LDH2 136
#define LDZ  36
#define GEMM_SMEM_BYTES 26112

__global__ __launch_bounds__(256) void gemm_wmma_kernel(
    const float* __restrict__ h, const float* __restrict__ W, int N)
{
    extern __shared__ char smraw[];
    __half* Ws  = reinterpret_cast<__half*>(smraw);           // [32][136]
    __half* hs  = reinterpret_cast<__half*>(smraw + 8704);    // [64][136]
    float*  zsm = reinterpret_cast<float*>(smraw + 8704);     // [64][36] alias

    const int tid  = threadIdx.x;
    const int wid  = tid >> 5;
    const int m0   = (wid & 3) * 16;
    const int n0   = (wid >> 2) * 16;
    const int row0 = blockIdx.x * 64;
    const unsigned FULL = 0xffffffffu;

    // ---- stage W -> fp16 smem ----
    const float4* W4 = reinterpret_cast<const float4*>(W);
    #pragma unroll
    for (int i = 0; i < 4; i++) {
        int f  = tid + i * 256;
        int n  = f >> 5;
        int k4 = f & 31;
        float4 v = __ldg(&W4[n * 32 + k4]);
        __half2 hx[2] = { __floats2half2_rn(v.x, v.y),
                          __floats2half2_rn(v.z, v.w) };
        *reinterpret_cast<uint2*>(&Ws[n * LDH2 + k4 * 4]) =
            *reinterpret_cast<const uint2*>(hx);
    }

    // ---- load 64-row h tile -> fp16 smem ----
    const float4* h4 = reinterpret_cast<const float4*>(h);
    #pragma unroll
    for (int i = 0; i < 8; i++) {
        int f    = tid + i * 256;
        int r    = f >> 5;
        int k4   = f & 31;
        int grow = row0 + r;
        if (grow >= N) grow = N - 1;
        float4 v = __ldg(&h4[grow * 32 + k4]);
        __half2 hx[2] = { __floats2half2_rn(v.x, v.y),
                          __floats2half2_rn(v.z, v.w) };
        *reinterpret_cast<uint2*>(&hs[r * LDH2 + k4 * 4]) =
            *reinterpret_cast<const uint2*>(hx);
    }
    __syncthreads();

    // ---- wmma: 1 m-tile x 1 n-tile x 8 k-steps per warp ----
    wmma::fragment<wmma::accumulator, 16, 16, 16, float> c0;
    wmma::fill_fragment(c0, 0.0f);
    wmma::fragment<wmma::matrix_a, 16, 16, 16, __half, wmma::row_major> a0;
    wmma::fragment<wmma::matrix_b, 16, 16, 16, __half, wmma::col_major> b0;
    #pragma unroll
    for (int ks = 0; ks < 8; ks++) {
        wmma::load_matrix_sync(a0, &hs[m0 * LDH2 + ks * 16], LDH2);
        wmma::load_matrix_sync(b0, &Ws[n0 * LDH2 + ks * 16], LDH2);
        wmma::mma_sync(c0, a0, b0, c0);
    }
    __syncthreads();

    wmma::store_matrix_sync(&zsm[m0 * LDZ + n0], c0, LDZ, wmma::mem_row_major);
    __syncthreads();

    // ---- epilogue: packed 128B row (fp16 z + fp32 inorm) ----
    // thread t: row = t>>2 (0..63), quarter q = t&3 -> dims 8q..8q+7
    int row = tid >> 2;
    int q   = tid & 3;
    float4 z4[2];
    z4[0] = *reinterpret_cast<const float4*>(&zsm[row * LDZ + q * 8]);
    z4[1] = *reinterpret_cast<const float4*>(&zsm[row * LDZ + q * 8 + 4]);
    float ss = z4[0].x * z4[0].x + z4[0].y * z4[0].y
             + z4[0].z * z4[0].z + z4[0].w * z4[0].w
             + z4[1].x * z4[1].x + z4[1].y * z4[1].y
             + z4[1].z * z4[1].z + z4[1].w * z4[1].w;
    ss += __shfl_xor_sync(FULL, ss, 1);
    ss += __shfl_xor_sync(FULL, ss, 2);
    int grow = row0 + row;
    if (grow < N) {
        __half2 hx[4];
        hx[0] = __floats2half2_rn(z4[0].x, z4[0].y);
        hx[1] = __floats2half2_rn(z4[0].z, z4[0].w);
        hx[2] = __floats2half2_rn(z4[1].x, z4[1].y);
        hx[3] = __floats2half2_rn(z4[1].z, z4[1].w);
        *reinterpret_cast<uint4*>(&g_rows[grow][2 * q]) =
            *reinterpret_cast<const uint4*>(hx);
        if (q == 0) {
            float inorm = 1.0f / fmaxf(sqrtf(ss), EPS);
            g_rows[grow][8] = make_uint2(__float_as_uint(inorm), 0u);
        }
    }
}

// ---------------------------------------------------------------------------
// Kernel 2: per-node cosine attention + softmax + weighted aggregation.
// Half-warp per node. Edge rows gathered as uint2/lane from one 128B line:
// lanes 0-7 carry 4 dims each, lane 8 carries the fp32 inorm, lanes 9-15 zero.
// The inorm rides THROUGH the 3-level pack-tree (lanes 8-15 group), so after
// one xor-8 shfl every lane holds (dot, inorm_s) of its edge; dot*inorm_s is
// symmetric so all 16 lanes compute valid esc -> single unpredicated STS.
// Gather order G (3-bit bit-reverse, involution) makes lane hl own edge hl.
// ---------------------------------------------------------------------------
__global__ __launch_bounds__(256) void edge_agg_kernel(
    const float* __restrict__ beta_p, const int* __restrict__ src,
    float* __restrict__ out, int N)
{
    __shared__ float alpha_sm[8][32];

    const int warp_id = (blockIdx.x * blockDim.x + threadIdx.x) >> 5;
    if (warp_id * 2 >= N) return;

    const int w    = threadIdx.x >> 5;
    const int lane = threadIdx.x & 31;
    const int half = lane >> 4;
    const int hl   = lane & 15;
    int node = warp_id * 2 + half;
    const bool valid = (node < N);
    if (!valid) node = N - 1;

    const unsigned FULL = 0xffffffffu;
    const float beta = __ldg(beta_p);

    // own row: lanes 0-7 -> zd dims 4hl..4hl+3, lane 8 -> inorm_d
    uint2 zraw = g_rows[node][hl];
    float inorm_d = __uint_as_float(
        __shfl_sync(FULL, zraw.x, (lane & 16) | 8));
    float2 zd0 = h2f(zraw.x);
    float2 zd1 = h2f(zraw.y);

    // src indices
    const int4* sp = reinterpret_cast<const int4*>(src + node * DEG);
    int4 s0 = __ldg(sp + 0);
    int4 s1 = __ldg(sp + 1);
    int4 s2 = __ldg(sp + 2);
    int4 s3 = __ldg(sp + 3);
    int si[DEG] = { s0.x, s0.y, s0.z, s0.w,  s1.x, s1.y, s1.z, s1.w,
                    s2.x, s2.y, s2.z, s2.w,  s3.x, s3.y, s3.z, s3.w };

    // gather order: edge of reg m is G[m]; G is an involution
    constexpr int G[16] = {0,4,2,6,1,5,3,7, 8,12,10,14,9,13,11,15};

    uint2 v[DEG];
    #pragma unroll
    for (int m = 0; m < DEG; m++)
        v[m] = g_rows[si[G[m]]][hl];

    // per-lane partials: data lanes -> 4-dim dot, lane 8 -> inorm, else 0
    float p[DEG];
    #pragma unroll
    for (int m = 0; m < DEG; m++) {
        float2 a = h2f(v[m].x);
        float2 b = h2f(v[m].y);
        float d = fmaf(a.x, zd0.x, fmaf(a.y, zd0.y,
                  fmaf(b.x, zd1.x, b.y * zd1.y)));
        p[m] = (hl < 8) ? d : ((hl == 8) ? __uint_as_float(v[m].x) : 0.0f);
    }

    // ---- 3-level pack-tree over 8-lane groups (28 shfl/warp) ----
    const bool b4 = (hl & 4) != 0;
    const bool b2 = (hl & 2) != 0;
    const bool b1 = (hl & 1) != 0;

    float s[8];
    #pragma unroll
    for (int i = 0; i < 8; i++) {
        float a = p[2 * i]     + __shfl_xor_sync(FULL, p[2 * i], 4);
        float b = p[2 * i + 1] + __shfl_xor_sync(FULL, p[2 * i + 1], 4);
        s[i] = b4 ? b : a;
    }
    float q[4];
    #pragma unroll
    for (int i = 0; i < 4; i++) {
        float a = s[2 * i]     + __shfl_xor_sync(FULL, s[2 * i], 2);
        float b = s[2 * i + 1] + __shfl_xor_sync(FULL, s[2 * i + 1], 2);
        q[i] = b2 ? b : a;
    }
    float r[2];
    #pragma unroll
    for (int i = 0; i < 2; i++) {
        float a = q[2 * i]     + __shfl_xor_sync(FULL, q[2 * i], 1);
        float b = q[2 * i + 1] + __shfl_xor_sync(FULL, q[2 * i + 1], 1);
        r[i] = b1 ? b : a;
    }
    // lane hl slot j: lanes 0-7 hold dot(edge (hl&7)+8j),
    //                 lanes 8-15 hold inorm_s(edge (hl&7)+8j)

    float esc[2];
    #pragma unroll
    for (int j = 0; j < 2; j++) {
        float other = __shfl_xor_sync(FULL, r[j], 8);
        float cosr  = r[j] * other * inorm_d;      // symmetric product
        esc[j] = __expf(beta * cosr);              // exp(beta*cos); const cancels
    }

    // lane hl publishes edge hl: slot = hl>>3
    alpha_sm[w][(lane & 16) | hl] = (hl & 8) ? esc[1] : esc[0];
    __syncwarp(FULL);

    // aggregation: lane hl<8 owns out dims 4hl..4hl+3
    const float4* ap = reinterpret_cast<const float4*>(&alpha_sm[w][lane & 16]);
    float o0 = 0.f, o1 = 0.f, o2 = 0.f, o3 = 0.f, denom = 0.f;
    #pragma unroll
    for (int e4 = 0; e4 < 4; e4++) {
        float4 a4 = ap[e4];
        denom += (a4.x + a4.y) + (a4.z + a4.w);
        #pragma unroll
        for (int t = 0; t < 4; t++) {
            int e = 4 * e4 + t;
            float af = (t == 0) ? a4.x : (t == 1) ? a4.y : (t == 2) ? a4.z : a4.w;
            uint2 vm = v[G[e]];                    // row data of edge e
            float2 va = h2f(vm.x);
            float2 vb = h2f(vm.y);
            o0 = fmaf(af, va.x, o0);
            o1 = fmaf(af, va.y, o1);
            o2 = fmaf(af, vb.x, o2);
            o3 = fmaf(af, vb.y, o3);
        }
    }

    if (valid && hl < 8) {
        float invd = 1.0f / denom;
        *reinterpret_cast<float4*>(&out[node * OUT_DIM + 4 * hl]) =
            make_float4(o0 * invd, o1 * invd, o2 * invd, o3 * invd);
    }
}

extern "C" void kernel_launch(void* const* d_in, const int* in_sizes, int n_in,
                              void* d_out, int out_size)
{
    const float* h    = (const float*)d_in[0];   // [N, 128]
    const float* W    = (const float*)d_in[1];   // [32, 128]
    const float* beta = (const float*)d_in[2];   // [1]
    const int*   src  = (const int*)d_in[3];     // [E]
    float* out = (float*)d_out;

    int N = in_sizes[0] / IN_DIM;                // 100000
    int ntiles = (N + 63) / 64;                  // 1563

    cudaFuncSetAttribute(gemm_wmma_kernel,
                         cudaFuncAttributeMaxDynamicSharedMemorySize,
                         GEMM_SMEM_BYTES);
    gemm_wmma_kernel<<<ntiles, 256, GEMM_SMEM_BYTES>>>(h, W, N);

    int nwarps  = (N + 1) / 2;
    int nblocks = (nwarps + 7) / 8;              // 8 warps / block
    edge_agg_kernel<<<nblocks, 256>>>(beta, src, out, N);
}

// round 14
// speedup vs baseline: 1.3668x; 1.3668x over previous
#include <cuda_runtime.h>
#include <cuda_fp16.h>
#include <mma.h>
#include <math.h>
#include <stdint.h>

using namespace nvcuda;

#define N_NODES   100000
#define DEG       16
#define IN_DIM    128
#define OUT_DIM   32
#define EPS       1e-8f

// scratch (device globals: no allocation allowed in kernel_launch)
__device__ __half2 g_zh[N_NODES * (OUT_DIM / 2)];   // z rows in fp16 (only copy)
__device__ float   g_inorm[N_NODES];                // 1 / max(||z_i||, EPS)

__device__ __forceinline__ float2 h2f(uint32_t u) {
    __half2 h = *reinterpret_cast<__half2*>(&u);
    return __half22float2(h);
}

// ---------------------------------------------------------------------------
// Kernel 1: z = h @ W^T via wmma FP16 (m16n16k16), fp32 accumulate, fused
// inverse row norms. (identical to R12 — at HBM floor)
// One CTA per 64-row tile (1563 CTAs), 256 threads = 8 warps, 26.1KB smem.
// ---------------------------------------------------------------------------
#define LDH2 136
#define LDZ  36
#define GEMM_SMEM_BYTES 26112

__global__ __launch_bounds__(256) void gemm_wmma_kernel(
    const float* __restrict__ h, const float* __restrict__ W, int N)
{
    extern __shared__ char smraw[];
    __half* Ws  = reinterpret_cast<__half*>(smraw);           // [32][136]
    __half* hs  = reinterpret_cast<__half*>(smraw + 8704);    // [64][136]
    float*  zsm = reinterpret_cast<float*>(smraw + 8704);     // [64][36] alias

    const int tid  = threadIdx.x;
    const int wid  = tid >> 5;
    const int m0   = (wid & 3) * 16;
    const int n0   = (wid >> 2) * 16;
    const int row0 = blockIdx.x * 64;
    const unsigned FULL = 0xffffffffu;

    // ---- stage W -> fp16 smem ----
    const float4* W4 = reinterpret_cast<const float4*>(W);
    #pragma unroll
    for (int i = 0; i < 4; i++) {
        int f  = tid + i * 256;
        int n  = f >> 5;
        int k4 = f & 31;
        float4 v = __ldg(&W4[n * 32 + k4]);
        __half2 hx[2] = { __floats2half2_rn(v.x, v.y),
                          __floats2half2_rn(v.z, v.w) };
        *reinterpret_cast<uint2*>(&Ws[n * LDH2 + k4 * 4]) =
            *reinterpret_cast<const uint2*>(hx);
    }

    // ---- load 64-row h tile -> fp16 smem ----
    const float4* h4 = reinterpret_cast<const float4*>(h);
    #pragma unroll
    for (int i = 0; i < 8; i++) {
        int f    = tid + i * 256;
        int r    = f >> 5;
        int k4   = f & 31;
        int grow = row0 + r;
        if (grow >= N) grow = N - 1;
        float4 v = __ldg(&h4[grow * 32 + k4]);
        __half2 hx[2] = { __floats2half2_rn(v.x, v.y),
                          __floats2half2_rn(v.z, v.w) };
        *reinterpret_cast<uint2*>(&hs[r * LDH2 + k4 * 4]) =
            *reinterpret_cast<const uint2*>(hx);
    }
    __syncthreads();

    // ---- wmma: 1 m-tile x 1 n-tile x 8 k-steps per warp ----
    wmma::fragment<wmma::accumulator, 16, 16, 16, float> c0;
    wmma::fill_fragment(c0, 0.0f);
    wmma::fragment<wmma::matrix_a, 16, 16, 16, __half, wmma::row_major> a0;
    wmma::fragment<wmma::matrix_b, 16, 16, 16, __half, wmma::col_major> b0;
    #pragma unroll
    for (int ks = 0; ks < 8; ks++) {
        wmma::load_matrix_sync(a0, &hs[m0 * LDH2 + ks * 16], LDH2);
        wmma::load_matrix_sync(b0, &Ws[n0 * LDH2 + ks * 16], LDH2);
        wmma::mma_sync(c0, a0, b0, c0);
    }
    __syncthreads();

    wmma::store_matrix_sync(&zsm[m0 * LDZ + n0], c0, LDZ, wmma::mem_row_major);
    __syncthreads();

    // ---- epilogue: fp16 z (coalesced) + inverse norms ----
    int row = tid >> 2;
    int q   = tid & 3;
    float4 z4[2];
    z4[0] = *reinterpret_cast<const float4*>(&zsm[row * LDZ + q * 8]);
    z4[1] = *reinterpret_cast<const float4*>(&zsm[row * LDZ + q * 8 + 4]);
    float ss = z4[0].x * z4[0].x + z4[0].y * z4[0].y
             + z4[0].z * z4[0].z + z4[0].w * z4[0].w
             + z4[1].x * z4[1].x + z4[1].y * z4[1].y
             + z4[1].z * z4[1].z + z4[1].w * z4[1].w;
    ss += __shfl_xor_sync(FULL, ss, 1);
    ss += __shfl_xor_sync(FULL, ss, 2);
    int grow = row0 + row;
    if (grow < N) {
        __half2 hx[4];
        hx[0] = __floats2half2_rn(z4[0].x, z4[0].y);
        hx[1] = __floats2half2_rn(z4[0].z, z4[0].w);
        hx[2] = __floats2half2_rn(z4[1].x, z4[1].y);
        hx[3] = __floats2half2_rn(z4[1].z, z4[1].w);
        *reinterpret_cast<uint4*>(&g_zh[grow * 16 + q * 4]) =
            *reinterpret_cast<const uint4*>(hx);
        if (q == 0)
            g_inorm[grow] = 1.0f / fmaxf(sqrtf(ss), EPS);
    }
}

// ---------------------------------------------------------------------------
// Kernel 2: per-node cosine attention + softmax + weighted aggregation.
// Half-warp per node, PARITY-SPLIT lanes: within a 16-lane half,
//   odd = hl>>3 (0: even edges, 1: odd edges), sub = hl&7 (4-dim chunk).
// Each lane gathers 8 rows as uint2 (4 dims of one edge per LDG; 8 LDGs).
// 3-level pack-tree over 8-lane subgroups (14 shfl/warp); with gather order
// R3[k]=rev3(k), lane `sub` ends owning the dot of edge 2*sub+odd, so the
// alpha STS slot is exactly `lane`. Parity halves combine via 4 xor-8 shfl.
// ---------------------------------------------------------------------------
__global__ __launch_bounds__(256) void edge_agg_kernel(
    const float* __restrict__ beta_p, const int* __restrict__ src,
    float* __restrict__ out, int N)
{
    __shared__ float alpha_sm[8][32];

    const int warp_id = (blockIdx.x * blockDim.x + threadIdx.x) >> 5;
    if (warp_id * 2 >= N) return;

    const int w    = threadIdx.x >> 5;
    const int lane = threadIdx.x & 31;
    const int half = lane >> 4;
    const int hl   = lane & 15;
    const int odd  = (hl >> 3) & 1;
    const int sub  = hl & 7;
    int node = warp_id * 2 + half;
    const bool valid = (node < N);
    if (!valid) node = N - 1;

    const unsigned FULL = 0xffffffffu;
    const float beta = __ldg(beta_p);
    const __half* zh = reinterpret_cast<const __half*>(g_zh);

    // own z chunk: dims 4*sub .. 4*sub+3
    uint2 zraw = *reinterpret_cast<const uint2*>(zh + node * 32 + 4 * sub);
    float2 zd0 = h2f(zraw.x);
    float2 zd1 = h2f(zraw.y);
    const float inv_nd = g_inorm[node];

    // all 16 src indices (uniform int4 loads)
    const int4* sp = reinterpret_cast<const int4*>(src + node * DEG);
    int4 s0 = __ldg(sp + 0);
    int4 s1 = __ldg(sp + 1);
    int4 s2 = __ldg(sp + 2);
    int4 s3 = __ldg(sp + 3);
    int si[DEG] = { s0.x, s0.y, s0.z, s0.w,  s1.x, s1.y, s1.z, s1.w,
                    s2.x, s2.y, s2.z, s2.w,  s3.x, s3.y, s3.z, s3.w };

    // gather order: item k = edge 2*R3[k] + odd  (R3 = 3-bit bit-reverse)
    constexpr int R3[8] = {0,4,2,6,1,5,3,7};
    int se[8];
    #pragma unroll
    for (int k = 0; k < 8; k++) {
        int e = 2 * R3[k];
        se[k] = odd ? si[e + 1] : si[e];
    }

    // own-edge (2*sub+odd) norm scale
    const int sid_own = __ldg(src + node * DEG + 2 * sub + odd);
    const float cc = __ldg(&g_inorm[sid_own]) * inv_nd;

    // gather: 4 dims of one edge per lane per LDG.64
    uint2 v[8];
    #pragma unroll
    for (int k = 0; k < 8; k++)
        v[k] = *reinterpret_cast<const uint2*>(zh + se[k] * 32 + 4 * sub);

    // per-lane 4-dim partial dots
    float p[8];
    #pragma unroll
    for (int k = 0; k < 8; k++) {
        float2 a = h2f(v[k].x);
        float2 b = h2f(v[k].y);
        p[k] = fmaf(a.x, zd0.x, fmaf(a.y, zd0.y,
               fmaf(b.x, zd1.x, b.y * zd1.y)));
    }

    // ---- 3-level pack-tree over 8-lane subgroups (14 shfl/warp) ----
    const bool c4 = (sub & 4) != 0;
    const bool c2 = (sub & 2) != 0;
    const bool c1 = (sub & 1) != 0;

    float s[4];
    #pragma unroll
    for (int i = 0; i < 4; i++) {
        float a = p[2 * i]     + __shfl_xor_sync(FULL, p[2 * i], 4);
        float b = p[2 * i + 1] + __shfl_xor_sync(FULL, p[2 * i + 1], 4);
        s[i] = c4 ? b : a;
    }
    float q[2];
    #pragma unroll
    for (int i = 0; i < 2; i++) {
        float a = s[2 * i]     + __shfl_xor_sync(FULL, s[2 * i], 2);
        float b = s[2 * i + 1] + __shfl_xor_sync(FULL, s[2 * i + 1], 2);
        q[i] = c2 ? b : a;
    }
    float ra = q[0] + __shfl_xor_sync(FULL, q[0], 1);
    float rb = q[1] + __shfl_xor_sync(FULL, q[1], 1);
    float dotv = c1 ? rb : ra;         // dot of edge 2*sub+odd

    // softmax weight: exp(beta*cos) (constant -beta cancels; bounded)
    float esc = __expf(beta * (dotv * cc));

    // slot hl = (odd<<3)|sub holds esc of edge 2*sub+odd
    alpha_sm[w][lane] = esc;
    __syncwarp(FULL);

    // read own parity block: slot s holds edge 2s+odd = alpha of v[R3[s]]
    const float4* ap = reinterpret_cast<const float4*>(&alpha_sm[w][lane & 24]);
    float4 A0 = ap[0];
    float4 A1 = ap[1];
    float d = (A0.x + A0.y) + (A0.z + A0.w) + (A1.x + A1.y) + (A1.z + A1.w);

    float o0 = 0.f, o1 = 0.f, o2 = 0.f, o3 = 0.f;
    #define ACC(af, vm) do {                                   \
        float2 va = h2f((vm).x);                               \
        float2 vb = h2f((vm).y);                               \
        o0 = fmaf((af), va.x, o0);  o1 = fmaf((af), va.y, o1); \
        o2 = fmaf((af), vb.x, o2);  o3 = fmaf((af), vb.y, o3); \
    } while (0)
    ACC(A0.x, v[0]);  ACC(A0.y, v[4]);  ACC(A0.z, v[2]);  ACC(A0.w, v[6]);
    ACC(A1.x, v[1]);  ACC(A1.y, v[5]);  ACC(A1.z, v[3]);  ACC(A1.w, v[7]);
    #undef ACC

    // combine parity halves (same sub, other odd)
    o0 += __shfl_xor_sync(FULL, o0, 8);
    o1 += __shfl_xor_sync(FULL, o1, 8);
    o2 += __shfl_xor_sync(FULL, o2, 8);
    o3 += __shfl_xor_sync(FULL, o3, 8);
    float denom = d + __shfl_xor_sync(FULL, d, 8);

    if (valid && odd == 0) {
        float invd = 1.0f / denom;
        *reinterpret_cast<float4*>(&out[node * OUT_DIM + 4 * sub]) =
            make_float4(o0 * invd, o1 * invd, o2 * invd, o3 * invd);
    }
}

extern "C" void kernel_launch(void* const* d_in, const int* in_sizes, int n_in,
                              void* d_out, int out_size)
{
    const float* h    = (const float*)d_in[0];   // [N, 128]
    const float* W    = (const float*)d_in[1];   // [32, 128]
    const float* beta = (const float*)d_in[2];   // [1]
    const int*   src  = (const int*)d_in[3];     // [E]
    float* out = (float*)d_out;

    int N = in_sizes[0] / IN_DIM;                // 100000
    int ntiles = (N + 63) / 64;                  // 1563

    cudaFuncSetAttribute(gemm_wmma_kernel,
                         cudaFuncAttributeMaxDynamicSharedMemorySize,
                         GEMM_SMEM_BYTES);
    gemm_wmma_kernel<<<ntiles, 256, GEMM_SMEM_BYTES>>>(h, W, N);

    int nwarps  = (N + 1) / 2;
    int nblocks = (nwarps + 7) / 8;              // 8 warps / block
    edge_agg_kernel<<<nblocks, 256>>>(beta, src, out, N);
}